// round 12
// baseline (speedup 1.0000x reference)
#include <cuda_runtime.h>
#include <cuda_fp16.h>
#include <cstdint>

// h (projected features) stored naturally [b][j][f] as fp16.
__device__ __align__(16) __half g_h_hi[4 * 2048 * 128];
__device__ float g_s[4 * 2048];

static __device__ __forceinline__ uint32_t smem_u32(const void* p) {
    uint32_t a;
    asm("{ .reg .u64 t; cvta.to.shared.u64 t, %1; cvt.u32.u64 %0, t; }" : "=r"(a) : "l"(p));
    return a;
}
static __device__ __forceinline__ void cp16(uint32_t dst, const void* src) {
    asm volatile("cp.async.cg.shared.global [%0], [%1], 16;" :: "r"(dst), "l"(src) : "memory");
}
static __device__ __forceinline__ void cp_commit() {
    asm volatile("cp.async.commit_group;" ::: "memory");
}
static __device__ __forceinline__ void cp_wait0() {
    asm volatile("cp.async.wait_group 0;" ::: "memory");
}
static __device__ __forceinline__ void ldsm4(uint32_t* r, uint32_t a) {
    asm volatile("ldmatrix.sync.aligned.m8n8.x4.shared.b16 {%0,%1,%2,%3}, [%4];"
                 : "=r"(r[0]), "=r"(r[1]), "=r"(r[2]), "=r"(r[3]) : "r"(a));
}
static __device__ __forceinline__ void ldsm4t(uint32_t* r, uint32_t a) {
    asm volatile("ldmatrix.sync.aligned.m8n8.x4.trans.shared.b16 {%0,%1,%2,%3}, [%4];"
                 : "=r"(r[0]), "=r"(r[1]), "=r"(r[2]), "=r"(r[3]) : "r"(a));
}
static __device__ __forceinline__ void mma16816(float* c, const uint32_t* a,
                                                uint32_t b0, uint32_t b1) {
    asm volatile(
        "mma.sync.aligned.m16n8k16.row.col.f32.f16.f16.f32 "
        "{%0,%1,%2,%3}, {%4,%5,%6,%7}, {%8,%9}, {%0,%1,%2,%3};"
        : "+f"(c[0]), "+f"(c[1]), "+f"(c[2]), "+f"(c[3])
        : "r"(a[0]), "r"(a[1]), "r"(a[2]), "r"(a[3]), "r"(b0), "r"(b1));
}
static __device__ __forceinline__ float leaky(float x) {
    return fmaxf(x, 0.f) + 0.2f * fminf(x, 0.f);
}
static __device__ __forceinline__ float ex2(float x) {
    float r; asm("ex2.approx.f32 %0, %1;" : "=f"(r) : "f"(x)); return r;
}

// ---------------- K1: h = x@W via fp16 hi/lo 3-pass HMMA, s = h@a_w + ab ---
static constexpr int XP       = 272;
static constexpr int OFF_XHI  = 0;
static constexpr int OFF_XLO  = OFF_XHI + 64 * XP;
static constexpr int OFF_WHI  = OFF_XLO + 64 * XP;
static constexpr int OFF_WLO  = OFF_WHI + 128 * XP;
static constexpr int OFF_AW   = OFF_WLO + 128 * XP;
static constexpr int OFF_SSM  = OFF_AW + 512;
static constexpr int SM1_SIZE = OFF_SSM + 256;

__global__ void __launch_bounds__(256) k_prep(const float* __restrict__ x,
                                              const float* __restrict__ W,
                                              const float* __restrict__ aw,
                                              const float* __restrict__ ab) {
    extern __shared__ char smp[];
    const uint32_t sbp = smem_u32(smp);
    const int tid = threadIdx.x, wid = tid >> 5, lane = tid & 31;
    const int b = blockIdx.x >> 5;
    const int i0 = (blockIdx.x & 31) * 64;

    const float4* xb = (const float4*)(x + ((size_t)b * 2048 + i0) * 128);
#pragma unroll
    for (int k = 0; k < 8; k++) {
        int idx = tid + 256 * k;
        int row = idx >> 5, c4 = idx & 31;
        float4 v = xb[idx];
        __half2 h0 = __floats2half2_rn(v.x, v.y);
        __half2 h1 = __floats2half2_rn(v.z, v.w);
        float2 f0 = __half22float2(h0), f1 = __half22float2(h1);
        __half2 l0 = __floats2half2_rn(v.x - f0.x, v.y - f0.y);
        __half2 l1 = __floats2half2_rn(v.z - f1.x, v.w - f1.y);
        char* d = smp + OFF_XHI + row * XP + c4 * 8;
        *(uint2*)d = make_uint2(*(uint32_t*)&h0, *(uint32_t*)&h1);
        *(uint2*)(d + (OFF_XLO - OFF_XHI)) = make_uint2(*(uint32_t*)&l0, *(uint32_t*)&l1);
    }
    const float4* wb = (const float4*)W;
#pragma unroll
    for (int k = 0; k < 16; k++) {
        int idx = tid + 256 * k;
        int row = idx >> 5, c4 = idx & 31;
        float4 v = wb[idx];
        __half2 h0 = __floats2half2_rn(v.x, v.y);
        __half2 h1 = __floats2half2_rn(v.z, v.w);
        float2 f0 = __half22float2(h0), f1 = __half22float2(h1);
        __half2 l0 = __floats2half2_rn(v.x - f0.x, v.y - f0.y);
        __half2 l1 = __floats2half2_rn(v.z - f1.x, v.w - f1.y);
        char* d = smp + OFF_WHI + row * XP + c4 * 8;
        *(uint2*)d = make_uint2(*(uint32_t*)&h0, *(uint32_t*)&h1);
        *(uint2*)(d + (OFF_WLO - OFF_WHI)) = make_uint2(*(uint32_t*)&l0, *(uint32_t*)&l1);
    }
    if (tid < 128) ((float*)(smp + OFF_AW))[tid] = aw[tid];
    if (tid < 64) ((float*)(smp + OFF_SSM))[tid] = 0.f;
    __syncthreads();

    const int r0 = (wid & 3) * 16, c0 = (wid >> 2) * 64;
    float acc[8][4];
#pragma unroll
    for (int nb = 0; nb < 8; nb++)
#pragma unroll
        for (int q = 0; q < 4; q++) acc[nb][q] = 0.f;

    const uint32_t arow = (uint32_t)((r0 + (lane & 15)) * XP + ((lane >> 4) << 4));
    const uint32_t brow = (uint32_t)((lane & 15) * XP + ((lane >> 4) << 4) + c0 * 2);
#pragma unroll
    for (int kk = 0; kk < 8; kk++) {
        uint32_t aph[4], apl[4];
        ldsm4(aph, sbp + OFF_XHI + arow + kk * 32);
        ldsm4(apl, sbp + OFF_XLO + arow + kk * 32);
        const uint32_t hb = sbp + OFF_WHI + brow + kk * 16 * XP;
#pragma unroll
        for (int n0 = 0; n0 < 4; n0++) {
            uint32_t bh[4], bl[4];
            ldsm4t(bh, hb + n0 * 32);
            ldsm4t(bl, hb + (OFF_WLO - OFF_WHI) + n0 * 32);
            mma16816(acc[2 * n0],     aph, bh[0], bh[1]);
            mma16816(acc[2 * n0 + 1], aph, bh[2], bh[3]);
            mma16816(acc[2 * n0],     apl, bh[0], bh[1]);
            mma16816(acc[2 * n0 + 1], apl, bh[2], bh[3]);
            mma16816(acc[2 * n0],     aph, bl[0], bl[1]);
            mma16816(acc[2 * n0 + 1], aph, bl[2], bl[3]);
        }
    }

    const float* awp = (const float*)(smp + OFF_AW);
    float* ssm = (float*)(smp + OFF_SSM);
    const int row_lo = r0 + (lane >> 2);
    __half* hout0 = g_h_hi + ((size_t)b * 2048 + i0 + row_lo) * 128;
    __half* hout1 = hout0 + 8 * 128;
    float s0 = 0.f, s1 = 0.f;
#pragma unroll
    for (int nb = 0; nb < 8; nb++) {
        const int col = c0 + nb * 8 + (lane & 3) * 2;
        __half2 o0 = __floats2half2_rn(acc[nb][0], acc[nb][1]);
        __half2 o1 = __floats2half2_rn(acc[nb][2], acc[nb][3]);
        *(uint32_t*)(hout0 + col) = *(uint32_t*)&o0;
        *(uint32_t*)(hout1 + col) = *(uint32_t*)&o1;
        s0 += acc[nb][0] * awp[col] + acc[nb][1] * awp[col + 1];
        s1 += acc[nb][2] * awp[col] + acc[nb][3] * awp[col + 1];
    }
    s0 += __shfl_xor_sync(0xffffffffu, s0, 1);
    s0 += __shfl_xor_sync(0xffffffffu, s0, 2);
    s1 += __shfl_xor_sync(0xffffffffu, s1, 1);
    s1 += __shfl_xor_sync(0xffffffffu, s1, 2);
    if ((lane & 3) == 0) {
        atomicAdd(&ssm[row_lo], s0);
        atomicAdd(&ssm[row_lo + 8], s1);
    }
    __syncthreads();
    if (tid < 64) g_s[b * 2048 + i0 + tid] = ssm[tid] + ab[0];
}

// ---------------- K2: fused exp->frag->HMMA, K-split warp pairs ------------
// 256 threads, 8 warps. warp w: rows (w&3)*16..+16 (x all 128 cols),
// K-parity g=w>>2 (even/odd 64-j chunks). P built in registers (no smem P).
// A + H streamed via cp.async into 4-stage rings; __syncthreads per step.
static constexpr int A_PITCH = 288;                   // 64 f32 + pad
static constexpr int ASB     = 64 * A_PITCH;          // 18432
static constexpr int H_PITCH = 272;                   // 128 halves + pad
static constexpr int HSB     = 64 * H_PITCH;          // 17408
static constexpr int OFF_AST = 0;                     // 4 stages A: 73728
static constexpr int OFF_HST = 4 * ASB;               // 73728; 4 stages H: 69632
static constexpr int OFF_SS   = OFF_HST + 4 * HSB;    // 143360 (2048 f)
static constexpr int OFF_BIAS = OFF_SS + 8192;        // 151552 (128 f)
static constexpr int OFF_LS   = OFF_BIAS + 512;       // 152064 (2x64 f)
static constexpr int OFF_SMAX = OFF_LS + 512;         // 152576
static constexpr int SM2_SIZE = OFF_SMAX + 16;        // 152592

__global__ void __launch_bounds__(256, 1) k_attn(const float* __restrict__ A,
                                                 const float* __restrict__ bias,
                                                 float* __restrict__ out) {
    extern __shared__ char sm[];
    const uint32_t sb = smem_u32(sm);
    const int tid = threadIdx.x, wid = tid >> 5, lane = tid & 31;
    const int b = blockIdx.x >> 5;
    const int i0 = (blockIdx.x & 31) << 6;
    const int g = wid >> 2;              // K-parity group
    const int r0w = (wid & 3) << 4;      // warp's 16 rows (tile-local)

    const float* Abase = A + ((size_t)b * 2048 + i0) * 2048;
    const __half* Hbase = g_h_hi + (size_t)b * 2048 * 128;

    // ---- issue cp.async for chunks 0,1 immediately ----
    const int ldrow = tid >> 2, ldc = tid & 3;
#pragma unroll
    for (int t = 0; t < 2; t++) {
        const int j0 = t * 64;
        const uint32_t aA = sb + OFF_AST + t * ASB + ldrow * A_PITCH + ldc * 64;
        const uint32_t aH = sb + OFF_HST + t * HSB + ldrow * H_PITCH + ldc * 64;
        const float*  sA = Abase + (size_t)ldrow * 2048 + j0 + ldc * 16;
        const __half* sH = Hbase + (size_t)(j0 + ldrow) * 128 + ldc * 32;
#pragma unroll
        for (int q = 0; q < 4; q++) {
            cp16(aA + q * 16, sA + q * 4);
            cp16(aH + q * 16, sH + q * 8);
        }
    }
    cp_commit();

    // ---- ss + bias ----
    float* ss = (float*)(sm + OFF_SS);
    {
        const float4* sg = (const float4*)(g_s + b * 2048);
        ((float4*)ss)[tid] = sg[tid];
        ((float4*)ss)[tid + 256] = sg[tid + 256];
        if (tid < 128) ((float*)(sm + OFF_BIAS))[tid] = bias[tid];
    }
    __syncthreads();

    // batch-wide max of s (fp16-safe shift)
    {
        float mx = -1e30f;
#pragma unroll
        for (int k = 0; k < 8; k++) mx = fmaxf(mx, ss[tid + 256 * k]);
#pragma unroll
        for (int off = 16; off >= 1; off >>= 1)
            mx = fmaxf(mx, __shfl_xor_sync(0xffffffffu, mx, off));
        if (lane == 0) ((float*)(sm + OFF_LS))[wid] = mx;
    }
    __syncthreads();
    if (tid == 0) {
        float mx = -1e30f;
#pragma unroll
        for (int w = 0; w < 8; w++) mx = fmaxf(mx, ((float*)(sm + OFF_LS))[w]);
        *(float*)(sm + OFF_SMAX) = mx;
    }
    __syncthreads();
    const float smax = *(const float*)(sm + OFF_SMAX);

    // per-thread row constants (MMA A-frag rows: rlo = lane>>2, rhi = +8)
    const int rlo = r0w + (lane >> 2);
    const int rhi = rlo + 8;
    const float C = 1.4426950408889634f;
    const float si_lo = ss[i0 + rlo], si_hi = ss[i0 + rhi];
    const float mc_lo = leaky(si_lo + smax) * C;
    const float mc_hi = leaky(si_hi + smax) * C;
    float lsum_lo = 0.f, lsum_hi = 0.f;

    float acc[16][4];
#pragma unroll
    for (int nb = 0; nb < 16; nb++)
#pragma unroll
        for (int q = 0; q < 4; q++) acc[nb][q] = 0.f;

    const int cjb = (lane & 3) * 2;
    const uint32_t brow = (uint32_t)((lane & 15) * H_PITCH + ((lane >> 4) << 4));

    cp_wait0();
    __syncthreads();

#pragma unroll 1
    for (int s = 0; s < 16; s++) {
        const int t = 2 * s + g;
        const int st = t & 3;
        const int j0 = t * 64;

        // prefetch chunks 2s+2, 2s+3 (stages not in use this step)
        if (s < 15) {
#pragma unroll
            for (int d = 2; d < 4; d++) {
                const int tn = 2 * s + d;
                const int stn = tn & 3;
                const int j0n = tn * 64;
                const uint32_t aA = sb + OFF_AST + stn * ASB + ldrow * A_PITCH + ldc * 64;
                const uint32_t aH = sb + OFF_HST + stn * HSB + ldrow * H_PITCH + ldc * 64;
                const float*  sA = Abase + (size_t)ldrow * 2048 + j0n + ldc * 16;
                const __half* sH = Hbase + (size_t)(j0n + ldrow) * 128 + ldc * 32;
#pragma unroll
                for (int q = 0; q < 4; q++) {
                    cp16(aA + q * 16, sA + q * 4);
                    cp16(aH + q * 16, sH + q * 8);
                }
            }
            cp_commit();
        }

        const char* Ast = sm + OFF_AST + st * ASB;
        const uint32_t aH = sb + OFF_HST + st * HSB;

#pragma unroll
        for (int kk = 0; kk < 4; kk++) {
            const int cj = kk * 16 + cjb;
            float2 f00 = *(const float2*)(Ast + rlo * A_PITCH + cj * 4);
            float2 f10 = *(const float2*)(Ast + rhi * A_PITCH + cj * 4);
            float2 f01 = *(const float2*)(Ast + rlo * A_PITCH + (cj + 8) * 4);
            float2 f11 = *(const float2*)(Ast + rhi * A_PITCH + (cj + 8) * 4);
            float2 sj0 = *(const float2*)(ss + j0 + cj);
            float2 sj1 = *(const float2*)(ss + j0 + cj + 8);

            float t0, mx, mn, lk, e;
            // 8 P values: rows {lo,hi} x cols {cj,cj+1,cj+8,cj+9}
            t0 = si_lo + sj0.x; mx = fmaxf(t0, 0.f); mn = fminf(t0, 0.f);
            lk = fmaf(0.2f, mn, mx); e = fmaf(f00.x, C, -mc_lo); e = fmaf(lk, C, e);
            float p00 = ex2(e);
            t0 = si_lo + sj0.y; mx = fmaxf(t0, 0.f); mn = fminf(t0, 0.f);
            lk = fmaf(0.2f, mn, mx); e = fmaf(f00.y, C, -mc_lo); e = fmaf(lk, C, e);
            float p01 = ex2(e);
            t0 = si_hi + sj0.x; mx = fmaxf(t0, 0.f); mn = fminf(t0, 0.f);
            lk = fmaf(0.2f, mn, mx); e = fmaf(f10.x, C, -mc_hi); e = fmaf(lk, C, e);
            float p10 = ex2(e);
            t0 = si_hi + sj0.y; mx = fmaxf(t0, 0.f); mn = fminf(t0, 0.f);
            lk = fmaf(0.2f, mn, mx); e = fmaf(f10.y, C, -mc_hi); e = fmaf(lk, C, e);
            float p11 = ex2(e);
            t0 = si_lo + sj1.x; mx = fmaxf(t0, 0.f); mn = fminf(t0, 0.f);
            lk = fmaf(0.2f, mn, mx); e = fmaf(f01.x, C, -mc_lo); e = fmaf(lk, C, e);
            float p08 = ex2(e);
            t0 = si_lo + sj1.y; mx = fmaxf(t0, 0.f); mn = fminf(t0, 0.f);
            lk = fmaf(0.2f, mn, mx); e = fmaf(f01.y, C, -mc_lo); e = fmaf(lk, C, e);
            float p09 = ex2(e);
            t0 = si_hi + sj1.x; mx = fmaxf(t0, 0.f); mn = fminf(t0, 0.f);
            lk = fmaf(0.2f, mn, mx); e = fmaf(f11.x, C, -mc_hi); e = fmaf(lk, C, e);
            float p18 = ex2(e);
            t0 = si_hi + sj1.y; mx = fmaxf(t0, 0.f); mn = fminf(t0, 0.f);
            lk = fmaf(0.2f, mn, mx); e = fmaf(f11.y, C, -mc_hi); e = fmaf(lk, C, e);
            float p19 = ex2(e);

            lsum_lo += (p00 + p01) + (p08 + p09);
            lsum_hi += (p10 + p11) + (p18 + p19);

            __half2 h0 = __floats2half2_rn(p00, p01);
            __half2 h1 = __floats2half2_rn(p10, p11);
            __half2 h2 = __floats2half2_rn(p08, p09);
            __half2 h3 = __floats2half2_rn(p18, p19);
            uint32_t af[4] = {*(uint32_t*)&h0, *(uint32_t*)&h1,
                              *(uint32_t*)&h2, *(uint32_t*)&h3};

            const uint32_t hb = aH + brow + kk * 16 * H_PITCH;
#pragma unroll
            for (int n0 = 0; n0 < 8; n0++) {
                uint32_t bh[4];
                ldsm4t(bh, hb + n0 * 32);
                mma16816(acc[2 * n0],     af, bh[0], bh[1]);
                mma16816(acc[2 * n0 + 1], af, bh[2], bh[3]);
            }
        }

        if (s < 15) cp_wait0();
        __syncthreads();
    }

    // ---- lsum reduction (4 lanes per row) ----
    lsum_lo += __shfl_xor_sync(0xffffffffu, lsum_lo, 1);
    lsum_lo += __shfl_xor_sync(0xffffffffu, lsum_lo, 2);
    lsum_hi += __shfl_xor_sync(0xffffffffu, lsum_hi, 1);
    lsum_hi += __shfl_xor_sync(0xffffffffu, lsum_hi, 2);
    float* ls2 = (float*)(sm + OFF_LS);
    if ((lane & 3) == 0) {
        ls2[g * 64 + rlo] = lsum_lo;
        ls2[g * 64 + rhi] = lsum_hi;
    }

    // ---- partial accumulator merge: group 1 -> smem scratch ----
    float4* scr = (float4*)sm;  // reuse A stages (32KB)
    if (g == 1) {
        float4* dst = scr + (wid & 3) * 512 + lane;
#pragma unroll
        for (int nb = 0; nb < 16; nb++) dst[nb * 32] = *(float4*)acc[nb];
    }
    __syncthreads();

    if (g == 0) {
        const float4* src = scr + (wid & 3) * 512 + lane;
        const float* bs = (const float*)(sm + OFF_BIAS);
        const float linv_lo = 1.0f / (ls2[rlo] + ls2[64 + rlo]);
        const float linv_hi = 1.0f / (ls2[rhi] + ls2[64 + rhi]);
        float* o_lo = out + ((size_t)b * 2048 + i0 + rlo) * 128;
        float* o_hi = out + ((size_t)b * 2048 + i0 + rhi) * 128;
#pragma unroll
        for (int nb = 0; nb < 16; nb++) {
            float4 pp = src[nb * 32];
            const int col = nb * 8 + (lane & 3) * 2;
            float2 v0 = make_float2((acc[nb][0] + pp.x) * linv_lo + bs[col],
                                    (acc[nb][1] + pp.y) * linv_lo + bs[col + 1]);
            float2 v1 = make_float2((acc[nb][2] + pp.z) * linv_hi + bs[col],
                                    (acc[nb][3] + pp.w) * linv_hi + bs[col + 1]);
            *(float2*)(o_lo + col) = v0;
            *(float2*)(o_hi + col) = v1;
        }
    }
}

extern "C" void kernel_launch(void* const* d_in, const int* in_sizes, int n_in,
                              void* d_out, int out_size) {
    (void)in_sizes; (void)n_in; (void)out_size;
    const float* x    = (const float*)d_in[0];
    const float* A    = (const float*)d_in[1];
    const float* W    = (const float*)d_in[2];
    const float* aw   = (const float*)d_in[3];
    const float* ab   = (const float*)d_in[4];
    const float* bias = (const float*)d_in[5];
    float* out = (float*)d_out;

    cudaFuncSetAttribute(k_prep, cudaFuncAttributeMaxDynamicSharedMemorySize, SM1_SIZE);
    cudaFuncSetAttribute(k_attn, cudaFuncAttributeMaxDynamicSharedMemorySize, SM2_SIZE);

    k_prep<<<128, 256, SM1_SIZE>>>(x, W, aw, ab);
    k_attn<<<128, 256, SM2_SIZE>>>(A, bias, out);
}

// round 13
// speedup vs baseline: 1.0202x; 1.0202x over previous
#include <cuda_runtime.h>
#include <cuda_fp16.h>
#include <cstdint>

// h (projected features) stored naturally [b][j][f] as fp16.
__device__ __align__(16) __half g_h_hi[4 * 2048 * 128];
__device__ float g_s[4 * 2048];

static __device__ __forceinline__ uint32_t smem_u32(const void* p) {
    uint32_t a;
    asm("{ .reg .u64 t; cvta.to.shared.u64 t, %1; cvt.u32.u64 %0, t; }" : "=r"(a) : "l"(p));
    return a;
}
static __device__ __forceinline__ void mbar_init(uint32_t a, uint32_t cnt) {
    asm volatile("mbarrier.init.shared.b64 [%0], %1;" :: "r"(a), "r"(cnt) : "memory");
}
static __device__ __forceinline__ void mbar_arrive(uint32_t a) {
    asm volatile("mbarrier.arrive.shared.b64 _, [%0];" :: "r"(a) : "memory");
}
static __device__ __forceinline__ void mbar_cp_arrive(uint32_t a) {
    asm volatile("cp.async.mbarrier.arrive.shared.b64 [%0];" :: "r"(a) : "memory");
}
static __device__ __forceinline__ void mbar_wait(uint32_t a, uint32_t par) {
    asm volatile(
        "{\n .reg .pred P;\n"
        "WL%=: mbarrier.try_wait.parity.shared.b64 P, [%0], %1;\n"
        " @P bra WD%=;\n bra WL%=;\n WD%=:\n}"
        :: "r"(a), "r"(par) : "memory");
}
static __device__ __forceinline__ void cp16(uint32_t dst, const void* src) {
    asm volatile("cp.async.cg.shared.global [%0], [%1], 16;" :: "r"(dst), "l"(src) : "memory");
}
static __device__ __forceinline__ void ldsm4(uint32_t* r, uint32_t a) {
    asm volatile("ldmatrix.sync.aligned.m8n8.x4.shared.b16 {%0,%1,%2,%3}, [%4];"
                 : "=r"(r[0]), "=r"(r[1]), "=r"(r[2]), "=r"(r[3]) : "r"(a));
}
static __device__ __forceinline__ void ldsm4t(uint32_t* r, uint32_t a) {
    asm volatile("ldmatrix.sync.aligned.m8n8.x4.trans.shared.b16 {%0,%1,%2,%3}, [%4];"
                 : "=r"(r[0]), "=r"(r[1]), "=r"(r[2]), "=r"(r[3]) : "r"(a));
}
static __device__ __forceinline__ void mma16816(float* c, const uint32_t* a,
                                                uint32_t b0, uint32_t b1) {
    asm volatile(
        "mma.sync.aligned.m16n8k16.row.col.f32.f16.f16.f32 "
        "{%0,%1,%2,%3}, {%4,%5,%6,%7}, {%8,%9}, {%0,%1,%2,%3};"
        : "+f"(c[0]), "+f"(c[1]), "+f"(c[2]), "+f"(c[3])
        : "r"(a[0]), "r"(a[1]), "r"(a[2]), "r"(a[3]), "r"(b0), "r"(b1));
}
static __device__ __forceinline__ float leaky(float x) {
    return fmaxf(x, 0.f) + 0.2f * fminf(x, 0.f);
}

// ---------------- K1: h = x@W via fp16 hi/lo 3-pass HMMA, s = h@a_w + ab ---
static constexpr int XP       = 272;
static constexpr int OFF_XHI  = 0;
static constexpr int OFF_XLO  = OFF_XHI + 64 * XP;
static constexpr int OFF_WHI  = OFF_XLO + 64 * XP;
static constexpr int OFF_WLO  = OFF_WHI + 128 * XP;
static constexpr int OFF_AW   = OFF_WLO + 128 * XP;
static constexpr int OFF_SSM  = OFF_AW + 512;
static constexpr int SM1_SIZE = OFF_SSM + 256;

__global__ void __launch_bounds__(256) k_prep(const float* __restrict__ x,
                                              const float* __restrict__ W,
                                              const float* __restrict__ aw,
                                              const float* __restrict__ ab) {
    extern __shared__ char smp[];
    const uint32_t sbp = smem_u32(smp);
    const int tid = threadIdx.x, wid = tid >> 5, lane = tid & 31;
    const int b = blockIdx.x >> 5;
    const int i0 = (blockIdx.x & 31) * 64;

    const float4* xb = (const float4*)(x + ((size_t)b * 2048 + i0) * 128);
#pragma unroll
    for (int k = 0; k < 8; k++) {
        int idx = tid + 256 * k;
        int row = idx >> 5, c4 = idx & 31;
        float4 v = xb[idx];
        __half2 h0 = __floats2half2_rn(v.x, v.y);
        __half2 h1 = __floats2half2_rn(v.z, v.w);
        float2 f0 = __half22float2(h0), f1 = __half22float2(h1);
        __half2 l0 = __floats2half2_rn(v.x - f0.x, v.y - f0.y);
        __half2 l1 = __floats2half2_rn(v.z - f1.x, v.w - f1.y);
        char* d = smp + OFF_XHI + row * XP + c4 * 8;
        *(uint2*)d = make_uint2(*(uint32_t*)&h0, *(uint32_t*)&h1);
        *(uint2*)(d + (OFF_XLO - OFF_XHI)) = make_uint2(*(uint32_t*)&l0, *(uint32_t*)&l1);
    }
    const float4* wb = (const float4*)W;
#pragma unroll
    for (int k = 0; k < 16; k++) {
        int idx = tid + 256 * k;
        int row = idx >> 5, c4 = idx & 31;
        float4 v = wb[idx];
        __half2 h0 = __floats2half2_rn(v.x, v.y);
        __half2 h1 = __floats2half2_rn(v.z, v.w);
        float2 f0 = __half22float2(h0), f1 = __half22float2(h1);
        __half2 l0 = __floats2half2_rn(v.x - f0.x, v.y - f0.y);
        __half2 l1 = __floats2half2_rn(v.z - f1.x, v.w - f1.y);
        char* d = smp + OFF_WHI + row * XP + c4 * 8;
        *(uint2*)d = make_uint2(*(uint32_t*)&h0, *(uint32_t*)&h1);
        *(uint2*)(d + (OFF_WLO - OFF_WHI)) = make_uint2(*(uint32_t*)&l0, *(uint32_t*)&l1);
    }
    if (tid < 128) ((float*)(smp + OFF_AW))[tid] = aw[tid];
    if (tid < 64) ((float*)(smp + OFF_SSM))[tid] = 0.f;
    __syncthreads();

    const int r0 = (wid & 3) * 16, c0 = (wid >> 2) * 64;
    float acc[8][4];
#pragma unroll
    for (int nb = 0; nb < 8; nb++)
#pragma unroll
        for (int q = 0; q < 4; q++) acc[nb][q] = 0.f;

    const uint32_t arow = (uint32_t)((r0 + (lane & 15)) * XP + ((lane >> 4) << 4));
    const uint32_t brow = (uint32_t)((lane & 15) * XP + ((lane >> 4) << 4) + c0 * 2);
#pragma unroll
    for (int kk = 0; kk < 8; kk++) {
        uint32_t aph[4], apl[4];
        ldsm4(aph, sbp + OFF_XHI + arow + kk * 32);
        ldsm4(apl, sbp + OFF_XLO + arow + kk * 32);
        const uint32_t hb = sbp + OFF_WHI + brow + kk * 16 * XP;
#pragma unroll
        for (int n0 = 0; n0 < 4; n0++) {
            uint32_t bh[4], bl[4];
            ldsm4t(bh, hb + n0 * 32);
            ldsm4t(bl, hb + (OFF_WLO - OFF_WHI) + n0 * 32);
            mma16816(acc[2 * n0],     aph, bh[0], bh[1]);
            mma16816(acc[2 * n0 + 1], aph, bh[2], bh[3]);
            mma16816(acc[2 * n0],     apl, bh[0], bh[1]);
            mma16816(acc[2 * n0 + 1], apl, bh[2], bh[3]);
            mma16816(acc[2 * n0],     aph, bl[0], bl[1]);
            mma16816(acc[2 * n0 + 1], aph, bl[2], bl[3]);
        }
    }

    const float* awp = (const float*)(smp + OFF_AW);
    float* ssm = (float*)(smp + OFF_SSM);
    const int row_lo = r0 + (lane >> 2);
    __half* hout0 = g_h_hi + ((size_t)b * 2048 + i0 + row_lo) * 128;
    __half* hout1 = hout0 + 8 * 128;
    float s0 = 0.f, s1 = 0.f;
#pragma unroll
    for (int nb = 0; nb < 8; nb++) {
        const int col = c0 + nb * 8 + (lane & 3) * 2;
        __half2 o0 = __floats2half2_rn(acc[nb][0], acc[nb][1]);
        __half2 o1 = __floats2half2_rn(acc[nb][2], acc[nb][3]);
        *(uint32_t*)(hout0 + col) = *(uint32_t*)&o0;
        *(uint32_t*)(hout1 + col) = *(uint32_t*)&o1;
        s0 += acc[nb][0] * awp[col] + acc[nb][1] * awp[col + 1];
        s1 += acc[nb][2] * awp[col] + acc[nb][3] * awp[col + 1];
    }
    s0 += __shfl_xor_sync(0xffffffffu, s0, 1);
    s0 += __shfl_xor_sync(0xffffffffu, s0, 2);
    s1 += __shfl_xor_sync(0xffffffffu, s1, 1);
    s1 += __shfl_xor_sync(0xffffffffu, s1, 2);
    if ((lane & 3) == 0) {
        atomicAdd(&ssm[row_lo], s0);
        atomicAdd(&ssm[row_lo + 8], s1);
    }
    __syncthreads();
    if (tid < 64) g_s[b * 2048 + i0 + tid] = ssm[tid] + ab[0];
}

// ---------------- K2: warp-specialized softmax + P@h, 8-stage ring ---------
// 512 threads: warps 0-7 = MMA (2 per SMSP), warps 8-15 = producers.
// H for chunk t+2 prefetched at iteration t (DRAM latency off critical path).
// Per stage: P[64][72]h (144B pitch), H[64][136]h (272B pitch).
static constexpr int NSTAGE  = 8;
static constexpr int P_PITCH = 144;
static constexpr int H_PITCH = 272;
static constexpr int OFF_HHI = 64 * P_PITCH;            // 9216
static constexpr int SBUF    = OFF_HHI + 64 * H_PITCH;  // 26624
static constexpr int OFF_SS   = NSTAGE * SBUF;          // 212992 (2048 f)
static constexpr int OFF_BIAS = OFF_SS + 8192;          // 221184 (128 f)
static constexpr int OFF_LS   = OFF_BIAS + 512;         // 221696 (64 f)
static constexpr int OFF_SMAX = OFF_LS + 256;           // 221952 (1 f)
static constexpr int OFF_MB   = OFF_SMAX + 16;          // 221968: full[8], empty[8]
static constexpr int SM2_SIZE = OFF_MB + 128;           // 222096

__global__ void __launch_bounds__(512) k_attn(const float* __restrict__ A,
                                              const float* __restrict__ bias,
                                              float* __restrict__ out) {
    extern __shared__ char sm[];
    const uint32_t sb = smem_u32(sm);
    const int tid = threadIdx.x, wid = tid >> 5, lane = tid & 31;
    const int b = blockIdx.x >> 5;
    const int i0 = (blockIdx.x & 31) << 6;

    float* ss = (float*)(sm + OFF_SS);
    {   // preload s for whole batch + bias
        const float4* sg = (const float4*)(g_s + b * 2048);
        float4* d = (float4*)ss;
        d[tid] = sg[tid];
        if (tid < 128) ((float*)(sm + OFF_BIAS))[tid] = bias[tid];
    }
    if (tid == 0) {
#pragma unroll
        for (int s = 0; s < NSTAGE; s++) {
            mbar_init(sb + OFF_MB + 8 * s, 256);                // full[s]
            mbar_init(sb + OFF_MB + 64 + 8 * s, 256);           // empty[s]
        }
    }
    __syncthreads();

    const __half* Hhig = g_h_hi + (size_t)b * 2048 * 128;
    const int pfc = (tid - 256) & 15, pjrb = (tid - 256) >> 4;

    // preamble: producers issue H for chunks 0,1 as early as possible
    if (wid >= 8) {
#pragma unroll
        for (int tc = 0; tc < 2; tc++) {
            const uint32_t bb = sb + tc * SBUF;
#pragma unroll
            for (int c = 0; c < 4; c++) {
                const int jr = pjrb + 16 * c;
                cp16(bb + OFF_HHI + jr * H_PITCH + pfc * 16,
                     Hhig + (size_t)(tc * 64 + jr) * 128 + pfc * 8);
            }
            mbar_cp_arrive(sb + OFF_MB + 8 * tc);
        }
    }

    // batch-wide max of s (fp16-safe shift)
    {
        float mx = -1e30f;
#pragma unroll
        for (int k = 0; k < 4; k++) mx = fmaxf(mx, ss[tid + 512 * k]);
#pragma unroll
        for (int off = 16; off >= 1; off >>= 1)
            mx = fmaxf(mx, __shfl_xor_sync(0xffffffffu, mx, off));
        if (lane == 0) ((float*)(sm + OFF_LS))[wid] = mx;
    }
    __syncthreads();
    if (tid == 0) {
        float mx = -1e30f;
#pragma unroll
        for (int w = 0; w < 16; w++) mx = fmaxf(mx, ((float*)(sm + OFF_LS))[w]);
        *(float*)(sm + OFF_SMAX) = mx;
    }
    __syncthreads();
    const float smax = *(const float*)(sm + OFF_SMAX);

    if (wid >= 8) {
        // ---------------- producer ----------------
        const int p = tid - 256;
        const int rbase = p >> 4, cbase = (p & 15) * 4;
        const float* Abase = A + ((size_t)b * 2048 + i0) * 2048;

        float s_i[4], m_i[4], lsum[4];
#pragma unroll
        for (int it = 0; it < 4; it++) {
            s_i[it] = ss[i0 + rbase + 16 * it];
            m_i[it] = leaky(s_i[it] + smax);
            lsum[it] = 0.f;
        }

        // A prefetch chunk 0
        float4 av[4];
#pragma unroll
        for (int it = 0; it < 4; it++)
            av[it] = *(const float4*)(Abase + (size_t)(rbase + 16 * it) * 2048 + cbase);

#pragma unroll 1
        for (int t = 0; t < 32; t++) {
            const int j0 = t * 64, st = t & (NSTAGE - 1);

            // prefetch H for chunk t+2 into stage (t+2)&7
            if (t < 30) {
                const int tn = t + 2;
                const int stn = tn & (NSTAGE - 1);
                const uint32_t pare = ((tn >> 3) + 1) & 1;
                mbar_wait(sb + OFF_MB + 64 + 8 * stn, pare);
                const uint32_t bbn = sb + stn * SBUF;
#pragma unroll
                for (int c = 0; c < 4; c++) {
                    const int jr = pjrb + 16 * c;
                    cp16(bbn + OFF_HHI + jr * H_PITCH + pfc * 16,
                         Hhig + (size_t)(tn * 64 + jr) * 128 + pfc * 8);
                }
                mbar_cp_arrive(sb + OFF_MB + 8 * stn);
            }

            // A prefetch for t+1
            const int j0n = (t < 31) ? (t + 1) * 64 : t * 64;
            float4 avn[4];
#pragma unroll
            for (int it = 0; it < 4; it++)
                avn[it] = *(const float4*)(Abase + (size_t)(rbase + 16 * it) * 2048 + j0n + cbase);

            // P for chunk t -> stage st (stage guaranteed free: waited at t-2)
            char* bp = sm + st * SBUF;
            const float4 sv = *(const float4*)(ss + j0 + cbase);
#pragma unroll
            for (int it = 0; it < 4; it++) {
                const float si = s_i[it], m = m_i[it];
                float e0 = leaky(si + sv.x) - m;
                float e1 = leaky(si + sv.y) - m;
                float e2 = leaky(si + sv.z) - m;
                float e3 = leaky(si + sv.w) - m;
                float p0 = __expf(e0 + av[it].x), p1 = __expf(e1 + av[it].y);
                float p2 = __expf(e2 + av[it].z), p3 = __expf(e3 + av[it].w);
                lsum[it] += (p0 + p1) + (p2 + p3);
                __half2 hA = __floats2half2_rn(p0, p1);
                __half2 hB = __floats2half2_rn(p2, p3);
                *(uint2*)(bp + (rbase + 16 * it) * P_PITCH + cbase * 2) =
                    make_uint2(*(uint32_t*)&hA, *(uint32_t*)&hB);
            }
            mbar_arrive(sb + OFF_MB + 8 * st);
#pragma unroll
            for (int it = 0; it < 4; it++) av[it] = avn[it];
        }

        // per-row sums -> smem (16 lanes share a row)
        float* ls = (float*)(sm + OFF_LS);
#pragma unroll
        for (int it = 0; it < 4; it++) {
            float v = lsum[it];
            v += __shfl_xor_sync(0xffffffffu, v, 1);
            v += __shfl_xor_sync(0xffffffffu, v, 2);
            v += __shfl_xor_sync(0xffffffffu, v, 4);
            v += __shfl_xor_sync(0xffffffffu, v, 8);
            if ((p & 15) == 0) ls[rbase + 16 * it] = v;
        }
    } else {
        // ---------------- consumer: 16 rows x 64 cols per warp -------------
        const int r0 = (wid & 3) * 16;       // SMSP = wid&3; 2 warps/SMSP
        const int c0 = (wid >> 2) * 64;
        float acc[8][4];
#pragma unroll
        for (int nb = 0; nb < 8; nb++)
#pragma unroll
            for (int q = 0; q < 4; q++) acc[nb][q] = 0.f;

        const uint32_t arow = (uint32_t)((r0 + (lane & 15)) * P_PITCH + ((lane >> 4) << 4));
        const uint32_t brow = (uint32_t)((lane & 15) * H_PITCH + ((lane >> 4) << 4) + c0 * 2);

#pragma unroll 1
        for (int t = 0; t < 32; t++) {
            const int st = t & (NSTAGE - 1);
            const uint32_t parf = (t >> 3) & 1;
            const uint32_t bb = sb + st * SBUF;
            mbar_wait(sb + OFF_MB + 8 * st, parf);

#pragma unroll
            for (int kk = 0; kk < 4; kk++) {
                uint32_t ap[4];
                ldsm4(ap, bb + arow + kk * 32);
                const uint32_t hb = bb + OFF_HHI + brow + kk * 16 * H_PITCH;
                uint32_t bh[4][4];
#pragma unroll
                for (int n0 = 0; n0 < 4; n0++) ldsm4t(bh[n0], hb + n0 * 32);
#pragma unroll
                for (int n0 = 0; n0 < 4; n0++) {
                    mma16816(acc[2 * n0],     ap, bh[n0][0], bh[n0][1]);
                    mma16816(acc[2 * n0 + 1], ap, bh[n0][2], bh[n0][3]);
                }
            }
            mbar_arrive(sb + OFF_MB + 64 + 8 * st);
        }

        __syncthreads();  // producers publish ls

        const float* ls = (const float*)(sm + OFF_LS);
        const float* bs = (const float*)(sm + OFF_BIAS);
        const int row_lo = r0 + (lane >> 2);
        const float linv0 = 1.0f / ls[row_lo];
        const float linv1 = 1.0f / ls[row_lo + 8];
        float* orow0 = out + ((size_t)b * 2048 + i0 + row_lo) * 128;
        float* orow1 = orow0 + 8 * 128;
#pragma unroll
        for (int nb = 0; nb < 8; nb++) {
            const int col = c0 + nb * 8 + (lane & 3) * 2;
            float2 o0 = make_float2(acc[nb][0] * linv0 + bs[col],
                                    acc[nb][1] * linv0 + bs[col + 1]);
            float2 o1 = make_float2(acc[nb][2] * linv1 + bs[col],
                                    acc[nb][3] * linv1 + bs[col + 1]);
            *(float2*)(orow0 + col) = o0;
            *(float2*)(orow1 + col) = o1;
        }
        return;  // consumers done (producers hit the syncthreads below)
    }
    __syncthreads();  // producers: pair with consumers' syncthreads
}

extern "C" void kernel_launch(void* const* d_in, const int* in_sizes, int n_in,
                              void* d_out, int out_size) {
    (void)in_sizes; (void)n_in; (void)out_size;
    const float* x    = (const float*)d_in[0];
    const float* A    = (const float*)d_in[1];
    const float* W    = (const float*)d_in[2];
    const float* aw   = (const float*)d_in[3];
    const float* ab   = (const float*)d_in[4];
    const float* bias = (const float*)d_in[5];
    float* out = (float*)d_out;

    cudaFuncSetAttribute(k_prep, cudaFuncAttributeMaxDynamicSharedMemorySize, SM1_SIZE);
    cudaFuncSetAttribute(k_attn, cudaFuncAttributeMaxDynamicSharedMemorySize, SM2_SIZE);

    k_prep<<<128, 256, SM1_SIZE>>>(x, W, aw, ab);
    k_attn<<<128, 512, SM2_SIZE>>>(A, bias, out);
}

// round 14
// speedup vs baseline: 1.3830x; 1.3556x over previous
#include <cuda_runtime.h>
#include <cuda_fp16.h>
#include <cstdint>

// h (projected features) stored naturally [b][j][f] as fp16.
__device__ __align__(16) __half g_h_hi[4 * 2048 * 128];
__device__ float g_s[4 * 2048];

static __device__ __forceinline__ uint32_t smem_u32(const void* p) {
    uint32_t a;
    asm("{ .reg .u64 t; cvta.to.shared.u64 t, %1; cvt.u32.u64 %0, t; }" : "=r"(a) : "l"(p));
    return a;
}
static __device__ __forceinline__ void cp16(uint32_t dst, const void* src) {
    asm volatile("cp.async.cg.shared.global [%0], [%1], 16;" :: "r"(dst), "l"(src) : "memory");
}
static __device__ __forceinline__ void cp_commit() {
    asm volatile("cp.async.commit_group;" ::: "memory");
}
template <int N> static __device__ __forceinline__ void cp_waitg() {
    asm volatile("cp.async.wait_group %0;" :: "n"(N) : "memory");
}
static __device__ __forceinline__ void ldsm4(uint32_t* r, uint32_t a) {
    asm volatile("ldmatrix.sync.aligned.m8n8.x4.shared.b16 {%0,%1,%2,%3}, [%4];"
                 : "=r"(r[0]), "=r"(r[1]), "=r"(r[2]), "=r"(r[3]) : "r"(a));
}
static __device__ __forceinline__ void ldsm4t(uint32_t* r, uint32_t a) {
    asm volatile("ldmatrix.sync.aligned.m8n8.x4.trans.shared.b16 {%0,%1,%2,%3}, [%4];"
                 : "=r"(r[0]), "=r"(r[1]), "=r"(r[2]), "=r"(r[3]) : "r"(a));
}
static __device__ __forceinline__ void mma16816(float* c, const uint32_t* a,
                                                uint32_t b0, uint32_t b1) {
    asm volatile(
        "mma.sync.aligned.m16n8k16.row.col.f32.f16.f16.f32 "
        "{%0,%1,%2,%3}, {%4,%5,%6,%7}, {%8,%9}, {%0,%1,%2,%3};"
        : "+f"(c[0]), "+f"(c[1]), "+f"(c[2]), "+f"(c[3])
        : "r"(a[0]), "r"(a[1]), "r"(a[2]), "r"(a[3]), "r"(b0), "r"(b1));
}
static __device__ __forceinline__ float leaky(float x) {
    return fmaxf(x, 0.f) + 0.2f * fminf(x, 0.f);
}

// ---------------- K1: h = x@W via fp16 hi/lo 3-pass HMMA, s = h@a_w + ab ---
static constexpr int XP       = 272;
static constexpr int OFF_XHI  = 0;
static constexpr int OFF_XLO  = OFF_XHI + 64 * XP;
static constexpr int OFF_WHI  = OFF_XLO + 64 * XP;
static constexpr int OFF_WLO  = OFF_WHI + 128 * XP;
static constexpr int OFF_AW   = OFF_WLO + 128 * XP;
static constexpr int OFF_SSM  = OFF_AW + 512;
static constexpr int SM1_SIZE = OFF_SSM + 256;

__global__ void __launch_bounds__(256) k_prep(const float* __restrict__ x,
                                              const float* __restrict__ W,
                                              const float* __restrict__ aw,
                                              const float* __restrict__ ab) {
    extern __shared__ char smp[];
    const uint32_t sbp = smem_u32(smp);
    const int tid = threadIdx.x, wid = tid >> 5, lane = tid & 31;
    const int b = blockIdx.x >> 5;
    const int i0 = (blockIdx.x & 31) * 64;

    const float4* xb = (const float4*)(x + ((size_t)b * 2048 + i0) * 128);
#pragma unroll
    for (int k = 0; k < 8; k++) {
        int idx = tid + 256 * k;
        int row = idx >> 5, c4 = idx & 31;
        float4 v = xb[idx];
        __half2 h0 = __floats2half2_rn(v.x, v.y);
        __half2 h1 = __floats2half2_rn(v.z, v.w);
        float2 f0 = __half22float2(h0), f1 = __half22float2(h1);
        __half2 l0 = __floats2half2_rn(v.x - f0.x, v.y - f0.y);
        __half2 l1 = __floats2half2_rn(v.z - f1.x, v.w - f1.y);
        char* d = smp + OFF_XHI + row * XP + c4 * 8;
        *(uint2*)d = make_uint2(*(uint32_t*)&h0, *(uint32_t*)&h1);
        *(uint2*)(d + (OFF_XLO - OFF_XHI)) = make_uint2(*(uint32_t*)&l0, *(uint32_t*)&l1);
    }
    const float4* wb = (const float4*)W;
#pragma unroll
    for (int k = 0; k < 16; k++) {
        int idx = tid + 256 * k;
        int row = idx >> 5, c4 = idx & 31;
        float4 v = wb[idx];
        __half2 h0 = __floats2half2_rn(v.x, v.y);
        __half2 h1 = __floats2half2_rn(v.z, v.w);
        float2 f0 = __half22float2(h0), f1 = __half22float2(h1);
        __half2 l0 = __floats2half2_rn(v.x - f0.x, v.y - f0.y);
        __half2 l1 = __floats2half2_rn(v.z - f1.x, v.w - f1.y);
        char* d = smp + OFF_WHI + row * XP + c4 * 8;
        *(uint2*)d = make_uint2(*(uint32_t*)&h0, *(uint32_t*)&h1);
        *(uint2*)(d + (OFF_WLO - OFF_WHI)) = make_uint2(*(uint32_t*)&l0, *(uint32_t*)&l1);
    }
    if (tid < 128) ((float*)(smp + OFF_AW))[tid] = aw[tid];
    if (tid < 64) ((float*)(smp + OFF_SSM))[tid] = 0.f;
    __syncthreads();

    const int r0 = (wid & 3) * 16, c0 = (wid >> 2) * 64;
    float acc[8][4];
#pragma unroll
    for (int nb = 0; nb < 8; nb++)
#pragma unroll
        for (int q = 0; q < 4; q++) acc[nb][q] = 0.f;

    const uint32_t arow = (uint32_t)((r0 + (lane & 15)) * XP + ((lane >> 4) << 4));
    const uint32_t brow = (uint32_t)((lane & 15) * XP + ((lane >> 4) << 4) + c0 * 2);
#pragma unroll
    for (int kk = 0; kk < 8; kk++) {
        uint32_t aph[4], apl[4];
        ldsm4(aph, sbp + OFF_XHI + arow + kk * 32);
        ldsm4(apl, sbp + OFF_XLO + arow + kk * 32);
        const uint32_t hb = sbp + OFF_WHI + brow + kk * 16 * XP;
#pragma unroll
        for (int n0 = 0; n0 < 4; n0++) {
            uint32_t bh[4], bl[4];
            ldsm4t(bh, hb + n0 * 32);
            ldsm4t(bl, hb + (OFF_WLO - OFF_WHI) + n0 * 32);
            mma16816(acc[2 * n0],     aph, bh[0], bh[1]);
            mma16816(acc[2 * n0 + 1], aph, bh[2], bh[3]);
            mma16816(acc[2 * n0],     apl, bh[0], bh[1]);
            mma16816(acc[2 * n0 + 1], apl, bh[2], bh[3]);
            mma16816(acc[2 * n0],     aph, bl[0], bl[1]);
            mma16816(acc[2 * n0 + 1], aph, bl[2], bl[3]);
        }
    }

    const float* awp = (const float*)(smp + OFF_AW);
    float* ssm = (float*)(smp + OFF_SSM);
    const int row_lo = r0 + (lane >> 2);
    __half* hout0 = g_h_hi + ((size_t)b * 2048 + i0 + row_lo) * 128;
    __half* hout1 = hout0 + 8 * 128;
    float s0 = 0.f, s1 = 0.f;
#pragma unroll
    for (int nb = 0; nb < 8; nb++) {
        const int col = c0 + nb * 8 + (lane & 3) * 2;
        __half2 o0 = __floats2half2_rn(acc[nb][0], acc[nb][1]);
        __half2 o1 = __floats2half2_rn(acc[nb][2], acc[nb][3]);
        *(uint32_t*)(hout0 + col) = *(uint32_t*)&o0;
        *(uint32_t*)(hout1 + col) = *(uint32_t*)&o1;
        s0 += acc[nb][0] * awp[col] + acc[nb][1] * awp[col + 1];
        s1 += acc[nb][2] * awp[col] + acc[nb][3] * awp[col + 1];
    }
    s0 += __shfl_xor_sync(0xffffffffu, s0, 1);
    s0 += __shfl_xor_sync(0xffffffffu, s0, 2);
    s1 += __shfl_xor_sync(0xffffffffu, s1, 1);
    s1 += __shfl_xor_sync(0xffffffffu, s1, 2);
    if ((lane & 3) == 0) {
        atomicAdd(&ssm[row_lo], s0);
        atomicAdd(&ssm[row_lo + 8], s1);
    }
    __syncthreads();
    if (tid < 64) g_s[b * 2048 + i0 + tid] = ssm[tid] + ab[0];
}

// ---------------- K2: lockstep warp-specialized pipeline, NO mbarriers -----
// 512 threads: warps 0-7 = MMA (2/SMSP), warps 8-15 = producers.
// Master loop t=0..32: producer builds P(t) (t<32) + prefetches H(t+2);
// consumer MMAs chunk t-1 (t>=1). One __syncthreads per iteration.
// P: 2 stages [64][72]h (144B pitch). H: 4 stages [64][136]h (272B pitch).
static constexpr int P_PITCH = 144;
static constexpr int H_PITCH = 272;
static constexpr int P_ST    = 64 * P_PITCH;        // 9216
static constexpr int H_ST    = 64 * H_PITCH;        // 17408
static constexpr int OFF_P   = 0;                   // 2 stages -> 18432
static constexpr int OFF_H   = 2 * P_ST;            // 18432; 4 stages -> 69632
static constexpr int OFF_SS   = OFF_H + 4 * H_ST;   // 88064 (2048 f)
static constexpr int OFF_BIAS = OFF_SS + 8192;      // 96256 (128 f)
static constexpr int OFF_LS   = OFF_BIAS + 512;     // 96768 (64 f)
static constexpr int OFF_SMAX = OFF_LS + 256;       // 97024 (1 f)
static constexpr int SM2_SIZE = OFF_SMAX + 16;      // 97040

__global__ void __launch_bounds__(512) k_attn(const float* __restrict__ A,
                                              const float* __restrict__ bias,
                                              float* __restrict__ out) {
    extern __shared__ char sm[];
    const uint32_t sb = smem_u32(sm);
    const int tid = threadIdx.x, wid = tid >> 5, lane = tid & 31;
    const int b = blockIdx.x >> 5;
    const int i0 = (blockIdx.x & 31) << 6;

    const __half* Hhig = g_h_hi + (size_t)b * 2048 * 128;
    const int p = tid - 256;                 // producer index (valid when wid>=8)
    const int pfc = p & 15, pjrb = p >> 4;

    // preamble: producers issue H(0), H(1) before anything else
    if (wid >= 8) {
#pragma unroll
        for (int tc = 0; tc < 2; tc++) {
            const uint32_t bb = sb + OFF_H + tc * H_ST;
#pragma unroll
            for (int c = 0; c < 4; c++) {
                const int jr = pjrb + 16 * c;
                cp16(bb + jr * H_PITCH + pfc * 16,
                     Hhig + (size_t)(tc * 64 + jr) * 128 + pfc * 8);
            }
            cp_commit();
        }
    }

    float* ss = (float*)(sm + OFF_SS);
    {   // preload s for whole batch + bias
        const float4* sg = (const float4*)(g_s + b * 2048);
        ((float4*)ss)[tid] = sg[tid];
        if (tid < 128) ((float*)(sm + OFF_BIAS))[tid] = bias[tid];
    }
    __syncthreads();

    // batch-wide max of s (fp16-safe shift)
    {
        float mx = -1e30f;
#pragma unroll
        for (int k = 0; k < 4; k++) mx = fmaxf(mx, ss[tid + 512 * k]);
#pragma unroll
        for (int off = 16; off >= 1; off >>= 1)
            mx = fmaxf(mx, __shfl_xor_sync(0xffffffffu, mx, off));
        if (lane == 0) ((float*)(sm + OFF_LS))[wid] = mx;
    }
    __syncthreads();
    if (tid == 0) {
        float mx = -1e30f;
#pragma unroll
        for (int w = 0; w < 16; w++) mx = fmaxf(mx, ((float*)(sm + OFF_LS))[w]);
        *(float*)(sm + OFF_SMAX) = mx;
    }
    __syncthreads();
    const float smax = *(const float*)(sm + OFF_SMAX);

    // ---- per-role persistent state ----
    // producer
    const int rbase = p >> 4, cbase = (p & 15) * 4;
    const float* Abase = A + ((size_t)b * 2048 + i0) * 2048;
    float s_i[4], m_i[4], lsum[4];
    float4 av[4];
    // consumer
    const int r0 = (wid & 3) * 16, c0 = (wid >> 2) * 64;
    float acc[8][4];
    const uint32_t arow = (uint32_t)((r0 + (lane & 15)) * P_PITCH + ((lane >> 4) << 4));
    const uint32_t brow = (uint32_t)((lane & 15) * H_PITCH + ((lane >> 4) << 4) + c0 * 2);

    if (wid >= 8) {
#pragma unroll
        for (int it = 0; it < 4; it++) {
            s_i[it] = ss[i0 + rbase + 16 * it];
            m_i[it] = leaky(s_i[it] + smax);
            lsum[it] = 0.f;
        }
#pragma unroll
        for (int it = 0; it < 4; it++)
            av[it] = *(const float4*)(Abase + (size_t)(rbase + 16 * it) * 2048 + cbase);
    } else {
#pragma unroll
        for (int nb = 0; nb < 8; nb++)
#pragma unroll
            for (int q = 0; q < 4; q++) acc[nb][q] = 0.f;
    }

#pragma unroll 1
    for (int t = 0; t <= 32; t++) {
        if (wid >= 8) {
            if (t < 32) {
                // prefetch H(t+2)
                if (t < 30) {
                    const uint32_t bbn = sb + OFF_H + ((t + 2) & 3) * H_ST;
#pragma unroll
                    for (int c = 0; c < 4; c++) {
                        const int jr = pjrb + 16 * c;
                        cp16(bbn + jr * H_PITCH + pfc * 16,
                             Hhig + (size_t)((t + 2) * 64 + jr) * 128 + pfc * 8);
                    }
                    cp_commit();
                }
                // A prefetch t+1
                const int j0n = (t < 31) ? (t + 1) * 64 : t * 64;
                float4 avn[4];
#pragma unroll
                for (int it = 0; it < 4; it++)
                    avn[it] = *(const float4*)(Abase + (size_t)(rbase + 16 * it) * 2048 + j0n + cbase);

                // P(t) -> stage t&1
                const int j0 = t * 64;
                char* bp = sm + OFF_P + (t & 1) * P_ST;
                const float4 sv = *(const float4*)(ss + j0 + cbase);
#pragma unroll
                for (int it = 0; it < 4; it++) {
                    const float si = s_i[it], m = m_i[it];
                    float e0 = leaky(si + sv.x) - m;
                    float e1 = leaky(si + sv.y) - m;
                    float e2 = leaky(si + sv.z) - m;
                    float e3 = leaky(si + sv.w) - m;
                    float p0 = __expf(e0 + av[it].x), p1 = __expf(e1 + av[it].y);
                    float p2 = __expf(e2 + av[it].z), p3 = __expf(e3 + av[it].w);
                    lsum[it] += (p0 + p1) + (p2 + p3);
                    __half2 hA = __floats2half2_rn(p0, p1);
                    __half2 hB = __floats2half2_rn(p2, p3);
                    *(uint2*)(bp + (rbase + 16 * it) * P_PITCH + cbase * 2) =
                        make_uint2(*(uint32_t*)&hA, *(uint32_t*)&hB);
                }
#pragma unroll
                for (int it = 0; it < 4; it++) av[it] = avn[it];

                // H(t) must be complete before next iteration's consumers use it
                if (t < 30)       cp_waitg<2>();
                else if (t == 30) cp_waitg<1>();
                else              cp_waitg<0>();
            }
        } else {
            if (t >= 1) {
                const int c = t - 1;
                const uint32_t pb = sb + OFF_P + (c & 1) * P_ST;
                const uint32_t hb0 = sb + OFF_H + (c & 3) * H_ST;
#pragma unroll
                for (int kk = 0; kk < 4; kk++) {
                    uint32_t ap[4];
                    ldsm4(ap, pb + arow + kk * 32);
                    const uint32_t hb = hb0 + brow + kk * 16 * H_PITCH;
                    uint32_t bh[4][4];
#pragma unroll
                    for (int n0 = 0; n0 < 4; n0++) ldsm4t(bh[n0], hb + n0 * 32);
#pragma unroll
                    for (int n0 = 0; n0 < 4; n0++) {
                        mma16816(acc[2 * n0],     ap, bh[n0][0], bh[n0][1]);
                        mma16816(acc[2 * n0 + 1], ap, bh[n0][2], bh[n0][3]);
                    }
                }
            }
        }
        __syncthreads();
    }

    // producers publish per-row sums
    if (wid >= 8) {
        float* ls = (float*)(sm + OFF_LS);
#pragma unroll
        for (int it = 0; it < 4; it++) {
            float v = lsum[it];
            v += __shfl_xor_sync(0xffffffffu, v, 1);
            v += __shfl_xor_sync(0xffffffffu, v, 2);
            v += __shfl_xor_sync(0xffffffffu, v, 4);
            v += __shfl_xor_sync(0xffffffffu, v, 8);
            if ((p & 15) == 0) ls[rbase + 16 * it] = v;
        }
    }
    __syncthreads();

    if (wid < 8) {
        const float* ls = (const float*)(sm + OFF_LS);
        const float* bs = (const float*)(sm + OFF_BIAS);
        const int row_lo = r0 + (lane >> 2);
        const float linv0 = 1.0f / ls[row_lo];
        const float linv1 = 1.0f / ls[row_lo + 8];
        float* orow0 = out + ((size_t)b * 2048 + i0 + row_lo) * 128;
        float* orow1 = orow0 + 8 * 128;
#pragma unroll
        for (int nb = 0; nb < 8; nb++) {
            const int col = c0 + nb * 8 + (lane & 3) * 2;
            float2 o0 = make_float2(acc[nb][0] * linv0 + bs[col],
                                    acc[nb][1] * linv0 + bs[col + 1]);
            float2 o1 = make_float2(acc[nb][2] * linv1 + bs[col],
                                    acc[nb][3] * linv1 + bs[col + 1]);
            *(float2*)(orow0 + col) = o0;
            *(float2*)(orow1 + col) = o1;
        }
    }
}

extern "C" void kernel_launch(void* const* d_in, const int* in_sizes, int n_in,
                              void* d_out, int out_size) {
    (void)in_sizes; (void)n_in; (void)out_size;
    const float* x    = (const float*)d_in[0];
    const float* A    = (const float*)d_in[1];
    const float* W    = (const float*)d_in[2];
    const float* aw   = (const float*)d_in[3];
    const float* ab   = (const float*)d_in[4];
    const float* bias = (const float*)d_in[5];
    float* out = (float*)d_out;

    cudaFuncSetAttribute(k_prep, cudaFuncAttributeMaxDynamicSharedMemorySize, SM1_SIZE);
    cudaFuncSetAttribute(k_attn, cudaFuncAttributeMaxDynamicSharedMemorySize, SM2_SIZE);

    k_prep<<<128, 256, SM1_SIZE>>>(x, W, aw, ab);
    k_attn<<<128, 512, SM2_SIZE>>>(A, bias, out);
}